// round 15
// baseline (speedup 1.0000x reference)
#include <cuda_runtime.h>
#include <math.h>

// BarycentricCoordinates: V=6000 x (R*A)=40 items, N=16 projections each.
// One thread per item.
//
// Bit-exactness model (validated R4-R14, rel_err == 0.0):
//  - einsum dot products (K=2): dot = __fmaf_rn(y,y', __fmul_rn(x,x'))
//  - all other elementwise ops: strict IEEE mul/sub/div/sqrt, no contraction.
//
// R15 = R14 (62.2us, no spills) + two chain-neutral hot-loop cuts:
//  - amax-form score (FMNMX abs modifiers are free): 5 ops -> 3.
//  - in-loop den==0 patch dropped (FSETP+SEL): den==0 pairs self-reject
//    (all gate products 0 -> m not > 0); covered by a cold exact full scan
//    (with the patch) whenever bestS stays INF after the exact epilogue.
// The exact-bit Gram body chains are deliberately UNCHANGED: R7-R13 showed
// shortening them (e.g. FFMA contraction) triggers ptxas over-pipelining and
// local-memory spills. Tracker stays int-key IMNMX (R14 win).

#define MULF(a,b)   __fmul_rn((a),(b))
#define ADDF(a,b)   __fadd_rn((a),(b))
#define SUBF(a,b)   __fsub_rn((a),(b))
#define DIVF(a,b)   __fdiv_rn((a),(b))
#define DOT2(ax,ay,bx,by) __fmaf_rn((ay),(by), __fmul_rn((ax),(bx)))

#define KEY_SENTINEL 0x7FFFFFFFu

__global__ __launch_bounds__(128, 5)
void bc_kernel(const float* __restrict__ tmpl,
               const float* __restrict__ proj,
               float* __restrict__ out, int V)
{
    __shared__ float2 s_e[16][128];   // (ex, ey)
    __shared__ float2 s_d[16][128];   // (d00, d02)
    __shared__ float  s_dist[16][128];

    const int RA = 40;
    int tid = threadIdx.x;
    int gid = blockIdx.x * blockDim.x + tid;
    if (gid >= V * RA) return;        // exact grid: never diverges
    int v  = gid / RA;
    int ra = gid - v * RA;

    float tx = __ldg(tmpl + 2 * ra);
    float ty = __ldg(tmpl + 2 * ra + 1);

    float px[16], py[16];
    const float4* pp = (const float4*)(proj + (size_t)v * 32);
    #pragma unroll
    for (int k = 0; k < 8; k++) {
        float4 q = __ldg(pp + k);
        px[2*k]   = q.x; py[2*k]   = q.y;
        px[2*k+1] = q.z; py[2*k+1] = q.w;
    }

    // dist: strict IEEE; stash in smem for the epilogue, regs die after scan.
    float dist[16];
    #pragma unroll
    for (int i = 0; i < 16; i++) {
        float dx = SUBF(tx, px[i]), dy = SUBF(ty, py[i]);
        dist[i] = __fsqrt_rn(ADDF(MULF(dx,dx), MULF(dy,dy)));
        s_dist[i][tid] = dist[i];
    }

    // Stable two-min scan (branchless): closest (bi,bx,by) and 2nd (si)
    float bd = dist[0], bx = px[0], by = py[0], sd = INFINITY;
    int bi = 0, si = 0;
    #pragma unroll
    for (int i = 1; i < 16; i++) {
        bool lb = dist[i] < bd;
        bool ls = dist[i] < sd;
        sd = lb ? bd : (ls ? dist[i] : sd);
        si = lb ? bi : (ls ? i       : si);
        bd = lb ? dist[i] : bd;
        bx = lb ? px[i]   : bx;
        by = lb ? py[i]   : by;
        bi = lb ? i       : bi;
    }

    float v2x = SUBF(tx, bx), v2y = SUBF(ty, by);
    float ex[16], ey[16], d00[16], d02[16];
    #pragma unroll
    for (int i = 0; i < 16; i++) {
        ex[i]  = SUBF(px[i], bx);
        ey[i]  = SUBF(py[i], by);
        d00[i] = DOT2(ex[i], ey[i], ex[i], ey[i]);
        d02[i] = DOT2(ex[i], ey[i], v2x, v2y);
        s_e[i][tid] = make_float2(ex[i], ey[i]);
        s_d[i][tid] = make_float2(d00[i], d02[i]);
    }

    // ---- approximate top-2 pair search: exact-bit body, int-key tracker ----
    unsigned k1 = KEY_SENTINEL, k2 = KEY_SENTINEL;

    #pragma unroll
    for (int i = 0; i < 15; i++) {
        #pragma unroll
        for (int j = i + 1; j < 16; j++) {
            float d01 = DOT2(ex[i], ey[i], ex[j], ey[j]);           // exact bits
            float den = SUBF(MULF(d00[i],d00[j]), MULF(d01,d01));   // exact bits
            float nA = SUBF(MULF(d02[i],d00[j]), MULF(d01,d02[j])); // exact bits
            float nB = SUBF(MULF(d00[i],d02[j]), MULF(d01,d02[i])); // exact bits
            float p0n  = SUBF(SUBF(den, nA), nB);     // ~ p0 * den (approx ok)
            float den2 = den * den;
            // sign-exact gates via products; conservative margin on p0.
            // den == 0 => all gates 0 => m not > 0 => self-reject (cold scan
            // covers the reference's den==0 -> 1e-10 patched winners).
            float gA = nA * den;
            float gB = nB * den;
            float gP = __fmaf_rn(p0n, den, 1e-5f * den2);
            float m  = fminf(fminf(gA, gB), gP);
            float am = fmaxf(fabsf(nA), fabsf(nB));   // FMNMX abs: free
            am = fmaxf(am, fabsf(p0n));
            float sNum = am * am;
            float r;
            asm("rcp.approx.f32 %0, %1;" : "=f"(r) : "f"(den2));    // MUFU pipe
            float s = sNum * r;                       // >= 0 when valid
            unsigned key = (m > 0.0f)
                ? ((__float_as_uint(s) & 0xFFFFFF00u) | (unsigned)(i * 16 + j))
                : KEY_SENTINEL;
            unsigned mx = umax(k1, key);              // IMNMX chain, lat 4
            k1 = umin(k1, key);
            k2 = umin(k2, mx);
        }
    }

    // ---- exact epilogue: re-evaluate top-2 candidates bit-exactly ----
    float w0 = 0.f, w1 = 0.f, w2 = 0.f;
    int   o1 = si, o2 = si;
    float bestS = INFINITY;

    #pragma unroll
    for (int c = 0; c < 2; c++) {
        unsigned key = (c == 0) ? k1 : k2;
        if (key != KEY_SENTINEL) {
            int code = (int)(key & 255u);
            int ip = code >> 4, jp = code & 15;
            float2 eiv = s_e[ip][tid], ejv = s_e[jp][tid];
            float2 div = s_d[ip][tid], djv = s_d[jp][tid];
            float  di  = s_dist[ip][tid], dj = s_dist[jp][tid];
            float d01 = DOT2(eiv.x, eiv.y, ejv.x, ejv.y);
            float den = SUBF(MULF(div.x,djv.x), MULF(d01,d01));
            if (den == 0.0f) den = 1e-10f;
            float nA = SUBF(MULF(div.y,djv.x), MULF(d01,djv.y));
            float nB = SUBF(MULF(div.x,djv.y), MULF(d01,div.y));
            bool candx = (den > 0.0f) ? (nA > 0.0f && nB > 0.0f)
                                      : (nA < 0.0f && nB < 0.0f);
            if (candx) {
                float pA = DIVF(nA, den);                 // exact IEEE divide
                float pB = DIVF(nB, den);
                float m2  = fmaxf(MULF(pA,pA), MULF(pB,pB));
                float p0i = SUBF(SUBF(1.0f, pA), pB);
                float p0j = SUBF(SUBF(1.0f, pB), pA);
                float siS = (p0i > 0.f) ? fmaxf(MULF(p0i,p0i), m2) : INFINITY;
                float sjS = (p0j > 0.f) ? fmaxf(MULF(p0j,p0j), m2) : INFINITY;
                bool iFirst = (di <= dj);
                float sLow  = iFirst ? siS : sjS;
                float sHigh = iFirst ? sjS : siS;
                bool pickLow = (sLow <= sHigh);
                float s = pickLow ? sLow : sHigh;
                if (s < bestS) {
                    bestS = s;
                    bool icell = pickLow ? iFirst : !iFirst;
                    if (icell) { w0 = p0i; w1 = pA; w2 = pB; o1 = ip; o2 = jp; }
                    else       { w0 = p0j; w1 = pB; w2 = pA; o1 = jp; o2 = ip; }
                }
            }
        }
    }

    // ---- cold safety net: no surviving candidate (incl. den==0-only items) ----
    if (!(bestS < INFINITY)) {
        #pragma unroll 1
        for (int ip = 0; ip < 15; ip++) {
            float2 eiv = s_e[ip][tid];
            float2 div = s_d[ip][tid];
            float  di  = s_dist[ip][tid];
            #pragma unroll 1
            for (int jp = ip + 1; jp < 16; jp++) {
                float2 ejv = s_e[jp][tid];
                float2 djv = s_d[jp][tid];
                float  dj  = s_dist[jp][tid];
                float d01 = DOT2(eiv.x, eiv.y, ejv.x, ejv.y);
                float den = SUBF(MULF(div.x,djv.x), MULF(d01,d01));
                if (den == 0.0f) den = 1e-10f;
                float nA = SUBF(MULF(div.y,djv.x), MULF(d01,djv.y));
                float nB = SUBF(MULF(div.x,djv.y), MULF(d01,div.y));
                bool candx = (den > 0.0f) ? (nA > 0.0f && nB > 0.0f)
                                          : (nA < 0.0f && nB < 0.0f);
                if (candx) {
                    float pA = DIVF(nA, den);
                    float pB = DIVF(nB, den);
                    float m2  = fmaxf(MULF(pA,pA), MULF(pB,pB));
                    float p0i = SUBF(SUBF(1.0f, pA), pB);
                    float p0j = SUBF(SUBF(1.0f, pB), pA);
                    float siS = (p0i > 0.f) ? fmaxf(MULF(p0i,p0i), m2) : INFINITY;
                    float sjS = (p0j > 0.f) ? fmaxf(MULF(p0j,p0j), m2) : INFINITY;
                    bool iFirst = (di <= dj);
                    float sLow  = iFirst ? siS : sjS;
                    float sHigh = iFirst ? sjS : siS;
                    bool pickLow = (sLow <= sHigh);
                    float s = pickLow ? sLow : sHigh;
                    if (s < bestS) {
                        bestS = s;
                        bool icell = pickLow ? iFirst : !iFirst;
                        if (icell) { w0 = p0i; w1 = pA; w2 = pB; o1 = ip; o2 = jp; }
                        else       { w0 = p0j; w1 = pB; w2 = pA; o1 = jp; o2 = ip; }
                    }
                }
            }
        }
        if (!(bestS < INFINITY)) {   // truly no valid pair: reference fallback
            w0 = 0.f; w1 = 0.f; w2 = 0.f; o1 = si; o2 = si;
        }
    }

    float* ow = out + (size_t)gid * 3;
    ow[0] = w0; ow[1] = w1; ow[2] = w2;
    float* oi = out + (size_t)V * RA * 3 + (size_t)gid * 3;
    oi[0] = (float)bi; oi[1] = (float)o1; oi[2] = (float)o2;
}

extern "C" void kernel_launch(void* const* d_in, const int* in_sizes, int n_in,
                              void* d_out, int out_size)
{
    const float* tmpl = (const float*)d_in[0];   // (5,8,2) = 80 floats
    const float* proj = (const float*)d_in[1];   // (V,16,2)
    int V = in_sizes[1] / 32;
    int total = V * 40;
    int threads = 128;
    int blocks = (total + threads - 1) / threads;
    bc_kernel<<<blocks, threads>>>(tmpl, proj, (float*)d_out, V);
}

// round 16
// speedup vs baseline: 1.6450x; 1.6450x over previous
#include <cuda_runtime.h>
#include <math.h>

// BarycentricCoordinates: V=6000 x (R*A)=40 items, N=16 projections each.
// One thread per item.
//
// Bit-exactness model (validated R4-R14, rel_err == 0.0):
//  - einsum dot products (K=2): dot = __fmaf_rn(y,y', __fmul_rn(x,x'))
//  - all other elementwise ops: strict IEEE mul/sub/div/sqrt, no contraction.
//
// R16 = R14 (62.2us, no spills) + ONE isolated off-chain cut:
//   score numerator via amax form: (max(|nA|,|nB|,|p0n|))^2 — FMNMX abs
//   modifiers are free, so 5 ops -> 3. Consumer-side only; every critical
//   chain (incl. the den==0 patch FSETP/FSEL, which doubles as a pipelining
//   throttle) is byte-identical to R14. R15 showed removing that patch
//   shortens the den chain and re-triggers spill-to-schedule; it stays.

#define MULF(a,b)   __fmul_rn((a),(b))
#define ADDF(a,b)   __fadd_rn((a),(b))
#define SUBF(a,b)   __fsub_rn((a),(b))
#define DIVF(a,b)   __fdiv_rn((a),(b))
#define DOT2(ax,ay,bx,by) __fmaf_rn((ay),(by), __fmul_rn((ax),(bx)))

#define KEY_SENTINEL 0x7FFFFFFFu

__global__ __launch_bounds__(128, 5)
void bc_kernel(const float* __restrict__ tmpl,
               const float* __restrict__ proj,
               float* __restrict__ out, int V)
{
    __shared__ float2 s_e[16][128];   // (ex, ey)
    __shared__ float2 s_d[16][128];   // (d00, d02)
    __shared__ float  s_dist[16][128];

    const int RA = 40;
    int tid = threadIdx.x;
    int gid = blockIdx.x * blockDim.x + tid;
    if (gid >= V * RA) return;        // exact grid: never diverges
    int v  = gid / RA;
    int ra = gid - v * RA;

    float tx = __ldg(tmpl + 2 * ra);
    float ty = __ldg(tmpl + 2 * ra + 1);

    float px[16], py[16];
    const float4* pp = (const float4*)(proj + (size_t)v * 32);
    #pragma unroll
    for (int k = 0; k < 8; k++) {
        float4 q = __ldg(pp + k);
        px[2*k]   = q.x; py[2*k]   = q.y;
        px[2*k+1] = q.z; py[2*k+1] = q.w;
    }

    // dist: strict IEEE; stash in smem for the epilogue, regs die after scan.
    float dist[16];
    #pragma unroll
    for (int i = 0; i < 16; i++) {
        float dx = SUBF(tx, px[i]), dy = SUBF(ty, py[i]);
        dist[i] = __fsqrt_rn(ADDF(MULF(dx,dx), MULF(dy,dy)));
        s_dist[i][tid] = dist[i];
    }

    // Stable two-min scan (branchless): closest (bi,bx,by) and 2nd (si)
    float bd = dist[0], bx = px[0], by = py[0], sd = INFINITY;
    int bi = 0, si = 0;
    #pragma unroll
    for (int i = 1; i < 16; i++) {
        bool lb = dist[i] < bd;
        bool ls = dist[i] < sd;
        sd = lb ? bd : (ls ? dist[i] : sd);
        si = lb ? bi : (ls ? i       : si);
        bd = lb ? dist[i] : bd;
        bx = lb ? px[i]   : bx;
        by = lb ? py[i]   : by;
        bi = lb ? i       : bi;
    }

    float v2x = SUBF(tx, bx), v2y = SUBF(ty, by);
    float ex[16], ey[16], d00[16], d02[16];
    #pragma unroll
    for (int i = 0; i < 16; i++) {
        ex[i]  = SUBF(px[i], bx);
        ey[i]  = SUBF(py[i], by);
        d00[i] = DOT2(ex[i], ey[i], ex[i], ey[i]);
        d02[i] = DOT2(ex[i], ey[i], v2x, v2y);
        s_e[i][tid] = make_float2(ex[i], ey[i]);
        s_d[i][tid] = make_float2(d00[i], d02[i]);
    }

    // ---- approximate top-2 pair search: exact-bit body, int-key tracker ----
    unsigned k1 = KEY_SENTINEL, k2 = KEY_SENTINEL;

    #pragma unroll
    for (int i = 0; i < 15; i++) {
        #pragma unroll
        for (int j = i + 1; j < 16; j++) {
            float d01 = DOT2(ex[i], ey[i], ex[j], ey[j]);           // exact bits
            float den = SUBF(MULF(d00[i],d00[j]), MULF(d01,d01));   // exact bits
            den = (den == 0.0f) ? 1e-10f : den;
            float nA = SUBF(MULF(d02[i],d00[j]), MULF(d01,d02[j])); // exact bits
            float nB = SUBF(MULF(d00[i],d02[j]), MULF(d01,d02[i])); // exact bits
            float p0n  = SUBF(SUBF(den, nA), nB);     // ~ p0 * den (approx ok)
            float den2 = den * den;
            // sign-exact gates via products; conservative margin on p0
            float gA = nA * den;
            float gB = nB * den;
            float gP = __fmaf_rn(p0n, den, 1e-5f * den2);
            float m  = fminf(fminf(gA, gB), gP);
            float am = fmaxf(fabsf(nA), fabsf(nB));   // FMNMX abs: free
            am = fmaxf(am, fabsf(p0n));
            float sNum = am * am;
            float r;
            asm("rcp.approx.f32 %0, %1;" : "=f"(r) : "f"(den2));    // MUFU pipe
            float s = sNum * r;                       // >= 0 when valid
            unsigned key = (m > 0.0f)
                ? ((__float_as_uint(s) & 0xFFFFFF00u) | (unsigned)(i * 16 + j))
                : KEY_SENTINEL;
            unsigned mx = umax(k1, key);              // IMNMX chain, lat 4
            k1 = umin(k1, key);
            k2 = umin(k2, mx);
        }
    }

    // ---- exact epilogue: re-evaluate top-2 candidates bit-exactly ----
    float w0 = 0.f, w1 = 0.f, w2 = 0.f;
    int   o1 = si, o2 = si;
    float bestS = INFINITY;

    #pragma unroll
    for (int c = 0; c < 2; c++) {
        unsigned key = (c == 0) ? k1 : k2;
        if (key != KEY_SENTINEL) {
            int code = (int)(key & 255u);
            int ip = code >> 4, jp = code & 15;
            float2 eiv = s_e[ip][tid], ejv = s_e[jp][tid];
            float2 div = s_d[ip][tid], djv = s_d[jp][tid];
            float  di  = s_dist[ip][tid], dj = s_dist[jp][tid];
            float d01 = DOT2(eiv.x, eiv.y, ejv.x, ejv.y);
            float den = SUBF(MULF(div.x,djv.x), MULF(d01,d01));
            if (den == 0.0f) den = 1e-10f;
            float nA = SUBF(MULF(div.y,djv.x), MULF(d01,djv.y));
            float nB = SUBF(MULF(div.x,djv.y), MULF(d01,div.y));
            bool candx = (den > 0.0f) ? (nA > 0.0f && nB > 0.0f)
                                      : (nA < 0.0f && nB < 0.0f);
            if (candx) {
                float pA = DIVF(nA, den);                 // exact IEEE divide
                float pB = DIVF(nB, den);
                float m2  = fmaxf(MULF(pA,pA), MULF(pB,pB));
                float p0i = SUBF(SUBF(1.0f, pA), pB);
                float p0j = SUBF(SUBF(1.0f, pB), pA);
                float siS = (p0i > 0.f) ? fmaxf(MULF(p0i,p0i), m2) : INFINITY;
                float sjS = (p0j > 0.f) ? fmaxf(MULF(p0j,p0j), m2) : INFINITY;
                bool iFirst = (di <= dj);
                float sLow  = iFirst ? siS : sjS;
                float sHigh = iFirst ? sjS : siS;
                bool pickLow = (sLow <= sHigh);
                float s = pickLow ? sLow : sHigh;
                if (s < bestS) {
                    bestS = s;
                    bool icell = pickLow ? iFirst : !iFirst;
                    if (icell) { w0 = p0i; w1 = pA; w2 = pB; o1 = ip; o2 = jp; }
                    else       { w0 = p0j; w1 = pB; w2 = pA; o1 = jp; o2 = ip; }
                }
            }
        }
    }

    if (!(bestS < INFINITY)) {   // no valid pair: reference fallback
        w0 = 0.f; w1 = 0.f; w2 = 0.f; o1 = si; o2 = si;
    }

    float* ow = out + (size_t)gid * 3;
    ow[0] = w0; ow[1] = w1; ow[2] = w2;
    float* oi = out + (size_t)V * RA * 3 + (size_t)gid * 3;
    oi[0] = (float)bi; oi[1] = (float)o1; oi[2] = (float)o2;
}

extern "C" void kernel_launch(void* const* d_in, const int* in_sizes, int n_in,
                              void* d_out, int out_size)
{
    const float* tmpl = (const float*)d_in[0];   // (5,8,2) = 80 floats
    const float* proj = (const float*)d_in[1];   // (V,16,2)
    int V = in_sizes[1] / 32;
    int total = V * 40;
    int threads = 128;
    int blocks = (total + threads - 1) / threads;
    bc_kernel<<<blocks, threads>>>(tmpl, proj, (float*)d_out, V);
}

// round 17
// speedup vs baseline: 1.7734x; 1.0780x over previous
#include <cuda_runtime.h>
#include <math.h>

// BarycentricCoordinates: V=6000 x (R*A)=40 items, N=16 projections each.
// One thread per item.
//
// Bit-exactness model (validated R4-R16, rel_err == 0.0):
//  - einsum dot products (K=2): dot = __fmaf_rn(y,y', __fmul_rn(x,x'))
//  - all other elementwise ops: strict IEEE mul/sub/div/sqrt, no contraction.
//
// R17 = R16 (60.1us, no spills) + closest-point compaction:
//   pairs containing the closest point bi have numerators EXACTLY 0 and are
//   always gate-rejected, so the hot loop now scans only the 15 other points
//   (C(15,2)=105 pairs vs 120). Compaction uses constant-index selects
//   (xc[t] = t<bi ? x[t] : x[t+1]); compacted values are bitwise copies and
//   d00c/d02c use the same DOT2 expressions -> identical bits -> identical
//   gating. Per-pair body is byte-identical to R16 (incl. den==0 patch, which
//   doubles as the pipelining throttle). Epilogue maps t -> t + (t >= bi).

#define MULF(a,b)   __fmul_rn((a),(b))
#define ADDF(a,b)   __fadd_rn((a),(b))
#define SUBF(a,b)   __fsub_rn((a),(b))
#define DIVF(a,b)   __fdiv_rn((a),(b))
#define DOT2(ax,ay,bx,by) __fmaf_rn((ay),(by), __fmul_rn((ax),(bx)))

#define KEY_SENTINEL 0x7FFFFFFFu

__global__ __launch_bounds__(128, 5)
void bc_kernel(const float* __restrict__ tmpl,
               const float* __restrict__ proj,
               float* __restrict__ out, int V)
{
    __shared__ float2 s_e[16][128];   // (ex, ey)        original indexing
    __shared__ float2 s_d[16][128];   // (d00, d02)      original indexing
    __shared__ float  s_dist[16][128];

    const int RA = 40;
    int tid = threadIdx.x;
    int gid = blockIdx.x * blockDim.x + tid;
    if (gid >= V * RA) return;        // exact grid: never diverges
    int v  = gid / RA;
    int ra = gid - v * RA;

    float tx = __ldg(tmpl + 2 * ra);
    float ty = __ldg(tmpl + 2 * ra + 1);

    float px[16], py[16];
    const float4* pp = (const float4*)(proj + (size_t)v * 32);
    #pragma unroll
    for (int k = 0; k < 8; k++) {
        float4 q = __ldg(pp + k);
        px[2*k]   = q.x; py[2*k]   = q.y;
        px[2*k+1] = q.z; py[2*k+1] = q.w;
    }

    // dist: strict IEEE; stash in smem for the epilogue, regs die after scan.
    float dist[16];
    #pragma unroll
    for (int i = 0; i < 16; i++) {
        float dx = SUBF(tx, px[i]), dy = SUBF(ty, py[i]);
        dist[i] = __fsqrt_rn(ADDF(MULF(dx,dx), MULF(dy,dy)));
        s_dist[i][tid] = dist[i];
    }

    // Stable two-min scan (branchless): closest (bi,bx,by) and 2nd (si)
    float bd = dist[0], bx = px[0], by = py[0], sd = INFINITY;
    int bi = 0, si = 0;
    #pragma unroll
    for (int i = 1; i < 16; i++) {
        bool lb = dist[i] < bd;
        bool ls = dist[i] < sd;
        sd = lb ? bd : (ls ? dist[i] : sd);
        si = lb ? bi : (ls ? i       : si);
        bd = lb ? dist[i] : bd;
        bx = lb ? px[i]   : bx;
        by = lb ? py[i]   : by;
        bi = lb ? i       : bi;
    }

    float v2x = SUBF(tx, bx), v2y = SUBF(ty, by);

    // originals -> smem (temps only; epilogue + cold scan use these)
    #pragma unroll
    for (int i = 0; i < 16; i++) {
        float e0 = SUBF(px[i], bx);
        float e1 = SUBF(py[i], by);
        s_e[i][tid] = make_float2(e0, e1);
        s_d[i][tid] = make_float2(DOT2(e0,e1,e0,e1), DOT2(e0,e1,v2x,v2y));
    }

    // compaction: skip the closest point (its pairs are always rejected).
    // exc[t] bitwise == ex[t + (t>=bi)], so all downstream bits are identical.
    float exc[15], eyc[15];
    #pragma unroll
    for (int t = 0; t < 15; t++) {
        bool lt = t < bi;
        float p0 = lt ? px[t] : px[t+1];
        float p1 = lt ? py[t] : py[t+1];
        exc[t] = SUBF(p0, bx);
        eyc[t] = SUBF(p1, by);
    }
    float d00c[15], d02c[15];
    #pragma unroll
    for (int t = 0; t < 15; t++) {
        d00c[t] = DOT2(exc[t], eyc[t], exc[t], eyc[t]);
        d02c[t] = DOT2(exc[t], eyc[t], v2x, v2y);
    }

    // ---- approximate top-2 pair search: 105 pairs, exact-bit body ----
    unsigned k1 = KEY_SENTINEL, k2 = KEY_SENTINEL;

    #pragma unroll
    for (int i = 0; i < 14; i++) {
        #pragma unroll
        for (int j = i + 1; j < 15; j++) {
            float d01 = DOT2(exc[i], eyc[i], exc[j], eyc[j]);          // exact bits
            float den = SUBF(MULF(d00c[i],d00c[j]), MULF(d01,d01));    // exact bits
            den = (den == 0.0f) ? 1e-10f : den;
            float nA = SUBF(MULF(d02c[i],d00c[j]), MULF(d01,d02c[j])); // exact bits
            float nB = SUBF(MULF(d00c[i],d02c[j]), MULF(d01,d02c[i])); // exact bits
            float p0n  = SUBF(SUBF(den, nA), nB);     // ~ p0 * den (approx ok)
            float den2 = den * den;
            // sign-exact gates via products; conservative margin on p0
            float gA = nA * den;
            float gB = nB * den;
            float gP = __fmaf_rn(p0n, den, 1e-5f * den2);
            float m  = fminf(fminf(gA, gB), gP);
            float am = fmaxf(fabsf(nA), fabsf(nB));   // FMNMX abs: free
            am = fmaxf(am, fabsf(p0n));
            float sNum = am * am;
            float r;
            asm("rcp.approx.f32 %0, %1;" : "=f"(r) : "f"(den2));       // MUFU pipe
            float s = sNum * r;                       // >= 0 when valid
            unsigned key = (m > 0.0f)
                ? ((__float_as_uint(s) & 0xFFFFFF00u) | (unsigned)(i * 16 + j))
                : KEY_SENTINEL;
            unsigned mx = umax(k1, key);              // IMNMX chain, lat 4
            k1 = umin(k1, key);
            k2 = umin(k2, mx);
        }
    }

    // ---- exact epilogue: re-evaluate top-2 candidates bit-exactly ----
    float w0 = 0.f, w1 = 0.f, w2 = 0.f;
    int   o1 = si, o2 = si;
    float bestS = INFINITY;

    #pragma unroll
    for (int c = 0; c < 2; c++) {
        unsigned key = (c == 0) ? k1 : k2;
        if (key != KEY_SENTINEL) {
            int code = (int)(key & 255u);
            int ip = code >> 4, jp = code & 15;
            ip += (ip >= bi);                 // compacted -> original index
            jp += (jp >= bi);
            float2 eiv = s_e[ip][tid], ejv = s_e[jp][tid];
            float2 div = s_d[ip][tid], djv = s_d[jp][tid];
            float  di  = s_dist[ip][tid], dj = s_dist[jp][tid];
            float d01 = DOT2(eiv.x, eiv.y, ejv.x, ejv.y);
            float den = SUBF(MULF(div.x,djv.x), MULF(d01,d01));
            if (den == 0.0f) den = 1e-10f;
            float nA = SUBF(MULF(div.y,djv.x), MULF(d01,djv.y));
            float nB = SUBF(MULF(div.x,djv.y), MULF(d01,div.y));
            bool candx = (den > 0.0f) ? (nA > 0.0f && nB > 0.0f)
                                      : (nA < 0.0f && nB < 0.0f);
            if (candx) {
                float pA = DIVF(nA, den);                 // exact IEEE divide
                float pB = DIVF(nB, den);
                float m2  = fmaxf(MULF(pA,pA), MULF(pB,pB));
                float p0i = SUBF(SUBF(1.0f, pA), pB);
                float p0j = SUBF(SUBF(1.0f, pB), pA);
                float siS = (p0i > 0.f) ? fmaxf(MULF(p0i,p0i), m2) : INFINITY;
                float sjS = (p0j > 0.f) ? fmaxf(MULF(p0j,p0j), m2) : INFINITY;
                bool iFirst = (di <= dj);
                float sLow  = iFirst ? siS : sjS;
                float sHigh = iFirst ? sjS : siS;
                bool pickLow = (sLow <= sHigh);
                float s = pickLow ? sLow : sHigh;
                if (s < bestS) {
                    bestS = s;
                    bool icell = pickLow ? iFirst : !iFirst;
                    if (icell) { w0 = p0i; w1 = pA; w2 = pB; o1 = ip; o2 = jp; }
                    else       { w0 = p0j; w1 = pB; w2 = pA; o1 = jp; o2 = ip; }
                }
            }
        }
    }

    if (!(bestS < INFINITY)) {   // no valid pair: reference fallback
        w0 = 0.f; w1 = 0.f; w2 = 0.f; o1 = si; o2 = si;
    }

    float* ow = out + (size_t)gid * 3;
    ow[0] = w0; ow[1] = w1; ow[2] = w2;
    float* oi = out + (size_t)V * RA * 3 + (size_t)gid * 3;
    oi[0] = (float)bi; oi[1] = (float)o1; oi[2] = (float)o2;
}

extern "C" void kernel_launch(void* const* d_in, const int* in_sizes, int n_in,
                              void* d_out, int out_size)
{
    const float* tmpl = (const float*)d_in[0];   // (5,8,2) = 80 floats
    const float* proj = (const float*)d_in[1];   // (V,16,2)
    int V = in_sizes[1] / 32;
    int total = V * 40;
    int threads = 128;
    int blocks = (total + threads - 1) / threads;
    bc_kernel<<<blocks, threads>>>(tmpl, proj, (float*)d_out, V);
}